// round 15
// baseline (speedup 1.0000x reference)
#include <cuda_runtime.h>
#include <stdint.h>
#include <math.h>

// ============================ problem constants ============================
#define NROW  8192
#define DIM   512
#define NS    4096
#define NTILE 64            // 8192 / 128
#define NPAIR 2080          // upper-triangular 128x128 tiles

// ============================ device scratch ===============================
__device__ __align__(16) float g_T[NROW * DIM];             // normalized rows (16 MB)
__device__ float  g_sq[NROW];                               // per-row sum of squares
__device__ __align__(16) float g_d2[(size_t)NPAIR * 16384]; // clamped d2 tiles (136 MB)
__device__ double g_sumd2;                                  // Σ d2 (all n² entries)
__device__ float  g_s0;                                     // 1/(16*bandwidth)
__device__ float  g_tsum[NPAIR];                            // per-tile fp32 kv sums (incl. diag)
__device__ float  g_ttr[NTILE];                             // per-diag-tile fp32 trace partials

// ============================ reductions ===================================
__device__ __forceinline__ double warpRedD(double v) {
    #pragma unroll
    for (int o = 16; o > 0; o >>= 1) v += __shfl_down_sync(0xffffffffu, v, o);
    return v;
}

__device__ __forceinline__ float warpRedF(float v) {
    #pragma unroll
    for (int o = 16; o > 0; o >>= 1) v += __shfl_down_sync(0xffffffffu, v, o);
    return v;
}

__device__ __forceinline__ float blockRed128(float v, float* sh) {
    #pragma unroll
    for (int o = 16; o > 0; o >>= 1) v += __shfl_down_sync(0xffffffffu, v, o);
    int wid = threadIdx.x >> 5, lid = threadIdx.x & 31;
    if (lid == 0) sh[wid] = v;
    __syncthreads();
    if (threadIdx.x == 0) sh[0] = sh[0] + sh[1] + sh[2] + sh[3];
    __syncthreads();
    float out = sh[0];
    __syncthreads();
    return out;
}

__device__ __forceinline__ int pair_idx(int ti, int tj) {
    return ti * NTILE - (ti * (ti - 1)) / 2 + (tj - ti);
}

// ============================ kernels ======================================

__global__ void k_zero() {
    if (threadIdx.x == 0) g_sumd2 = 0.0;
}

// Normalize rows (fp32, exactly as reference), store t and sq.
__global__ void k_norm(const float* __restrict__ src, const float* __restrict__ tgt) {
    __shared__ float sh[4];
    int r = blockIdx.x;
    const float* x = (r < NS) ? (src + (size_t)r * DIM) : (tgt + (size_t)(r - NS) * DIM);
    int tid = threadIdx.x;  // 128 threads, 4 elems each

    float v[4]; float s = 0.f;
    #pragma unroll
    for (int i = 0; i < 4; i++) { v[i] = x[tid + i * 128]; s += v[i] * v[i]; }
    s = blockRed128(s, sh);
    float dn = fmaxf(sqrtf(s), 1e-12f);

    float sq = 0.f;
    #pragma unroll
    for (int i = 0; i < 4; i++) {
        float t = v[i] / dn;
        sq += t * t;
        g_T[(size_t)r * DIM + tid + i * 128] = t;
    }
    sq = blockRed128(sq, sh);
    if (tid == 0) g_sq[r] = sq;
}

// ------------------------------------------------------------------
// Pass A: fp32 SIMT gram, 128x128 tile, 256 threads, 8x8 per thread.
// Stores clamped d2 per tile and accumulates Σd2 (weight 2 off-diag).
// ------------------------------------------------------------------
__global__ void __launch_bounds__(256, 2) k_gram() {
    int ti = blockIdx.y, tj = blockIdx.x;
    if (tj < ti) return;

    __shared__ float As[16][132];
    __shared__ float Bs[16][132];
    __shared__ float sqi[128], sqj[128];
    __shared__ double sred[8];

    int tid = threadIdx.x;
    if (tid < 128) sqi[tid]       = g_sq[ti * 128 + tid];
    else           sqj[tid - 128] = g_sq[tj * 128 + (tid - 128)];

    float acc[8][8];
    #pragma unroll
    for (int i = 0; i < 8; i++)
        #pragma unroll
        for (int j = 0; j < 8; j++) acc[i][j] = 0.f;

    const float* TA = g_T + (size_t)ti * 128 * DIM;
    const float* TB = g_T + (size_t)tj * 128 * DIM;

    int tm = (tid >> 4) << 3;
    int tn = (tid & 15) << 3;
    int lr = tid >> 1;
    int lc = (tid & 1) << 3;

    #pragma unroll 1
    for (int k0 = 0; k0 < DIM; k0 += 16) {
        __syncthreads();
        float4 a0 = *(const float4*)(TA + (size_t)lr * DIM + k0 + lc);
        float4 a1 = *(const float4*)(TA + (size_t)lr * DIM + k0 + lc + 4);
        float4 b0 = *(const float4*)(TB + (size_t)lr * DIM + k0 + lc);
        float4 b1 = *(const float4*)(TB + (size_t)lr * DIM + k0 + lc + 4);
        As[lc + 0][lr] = a0.x; As[lc + 1][lr] = a0.y;
        As[lc + 2][lr] = a0.z; As[lc + 3][lr] = a0.w;
        As[lc + 4][lr] = a1.x; As[lc + 5][lr] = a1.y;
        As[lc + 6][lr] = a1.z; As[lc + 7][lr] = a1.w;
        Bs[lc + 0][lr] = b0.x; Bs[lc + 1][lr] = b0.y;
        Bs[lc + 2][lr] = b0.z; Bs[lc + 3][lr] = b0.w;
        Bs[lc + 4][lr] = b1.x; Bs[lc + 5][lr] = b1.y;
        Bs[lc + 6][lr] = b1.z; Bs[lc + 7][lr] = b1.w;
        __syncthreads();

        #pragma unroll
        for (int kk = 0; kk < 16; ++kk) {
            float4 av0 = *(const float4*)(&As[kk][tm]);
            float4 av1 = *(const float4*)(&As[kk][tm + 4]);
            float4 bv0 = *(const float4*)(&Bs[kk][tn]);
            float4 bv1 = *(const float4*)(&Bs[kk][tn + 4]);
            float a[8] = { av0.x, av0.y, av0.z, av0.w, av1.x, av1.y, av1.z, av1.w };
            float b[8] = { bv0.x, bv0.y, bv0.z, bv0.w, bv1.x, bv1.y, bv1.z, bv1.w };
            #pragma unroll
            for (int i = 0; i < 8; i++)
                #pragma unroll
                for (int j = 0; j < 8; j++)
                    acc[i][j] = fmaf(a[i], b[j], acc[i][j]);
        }
    }

    size_t base = (size_t)pair_idx(ti, tj) * 16384;
    double dsum = 0.0;
    #pragma unroll
    for (int i = 0; i < 8; i++) {
        #pragma unroll
        for (int j = 0; j < 8; j++) {
            int gi = tm + i, gj = tn + j;
            float d2 = fmaxf(sqi[gi] + sqj[gj] - 2.0f * acc[i][j], 0.0f);
            g_d2[base + (size_t)gi * 128 + gj] = d2;
            dsum += (double)d2;
        }
    }
    if (ti != tj) dsum *= 2.0;

    dsum = warpRedD(dsum);
    int w = tid >> 5, lane = tid & 31;
    if (lane == 0) sred[w] = dsum;
    __syncthreads();
    if (tid == 0) {
        double t = 0.0;
        #pragma unroll
        for (int i = 0; i < 8; i++) t += sred[i];
        atomicAdd(&g_sumd2, t);
    }
}

// bandwidth per reference: sum(d2)/(n²−n) + EPS, then /4
__global__ void k_bw() {
    if (threadIdx.x == 0) {
        double n = (double)NROW;
        double bw = g_sumd2 / (n * n - n) + 1e-8;
        bw *= 0.25;
        g_s0 = (float)(1.0 / (bw * 16.0));
    }
}

// ------------------------------------------------------------------
// Pass B: per-tile kv sums INCLUDING the diagonal (like ref's sum(XX)),
// accumulated in fp32 deterministic trees (reference-faithful precision).
// Also per-diagonal-tile fp32 trace partials.
// ------------------------------------------------------------------
__global__ void __launch_bounds__(256) k_kv() {
    int ti = blockIdx.y, tj = blockIdx.x;
    if (tj < ti) return;

    __shared__ float sred[8];
    __shared__ float str[4];
    int tid = threadIdx.x;
    const float* d2p = g_d2 + (size_t)pair_idx(ti, tj) * 16384;
    float s0 = g_s0;

    // thread t sums contiguous entries [t*64, t*64+64) sequentially in fp32
    float a = 0.f;
    #pragma unroll 4
    for (int e = tid * 64; e < tid * 64 + 64; ++e) {
        float d2 = d2p[e];
        float e4 = expf(-d2 * s0);
        float e3 = e4 * e4, e2 = e3 * e3, e1 = e2 * e2, e0 = e1 * e1;
        a += ((e0 + e1) + (e2 + e3)) + e4;   // kv, diagonal included
    }
    a = warpRedF(a);
    int w = tid >> 5, lane = tid & 31;
    if (lane == 0) sred[w] = a;
    __syncthreads();
    if (tid == 0) {
        float s = ((sred[0] + sred[1]) + (sred[2] + sred[3]))
                + ((sred[4] + sred[5]) + (sred[6] + sred[7]));
        g_tsum[pair_idx(ti, tj)] = s;
    }

    // trace partial for diagonal tiles (fp32 tree over 128 diag entries)
    if (ti == tj) {
        float tr = 0.f;
        if (tid < 128) {
            float d2 = d2p[tid * 129];           // (i,i)
            float e4 = expf(-d2 * s0);
            float e3 = e4 * e4, e2 = e3 * e3, e1 = e2 * e2, e0 = e1 * e1;
            tr = ((e0 + e1) + (e2 + e3)) + e4;
        }
        tr = warpRedF(tr);
        if (tid < 128 && lane == 0) str[w] = tr;
        __syncthreads();
        if (tid == 0)
            g_ttr[ti] = (str[0] + str[1]) + (str[2] + str[3]);
    }
}

// ------------------------------------------------------------------
// Final: region sums via fp32 pairwise trees over tile sums (mirrors
// counted as separate leaves), trace subtraction and loss in fp32 —
// mirroring the reference's fp32 arithmetic structure.
// ------------------------------------------------------------------
__global__ void __launch_bounds__(1024) k_final(float* out) {
    __shared__ float sm[1024];
    int tid = threadIdx.x;
    int a = tid >> 5, b = tid & 31;

    // ---- S_XX: all 32x32 ordered tile pairs in region [0,32) ----
    {
        int lo = min(a, b), hi = max(a, b);
        sm[tid] = g_tsum[pair_idx(lo, hi)];
    }
    __syncthreads();
    for (int s = 512; s > 0; s >>= 1) {
        if (tid < s) sm[tid] += sm[tid + s];
        __syncthreads();
    }
    float S_XX = sm[0];
    __syncthreads();

    // ---- S_YY ----
    {
        int lo = 32 + min(a, b), hi = 32 + max(a, b);
        sm[tid] = g_tsum[pair_idx(lo, hi)];
    }
    __syncthreads();
    for (int s = 512; s > 0; s >>= 1) {
        if (tid < s) sm[tid] += sm[tid + s];
        __syncthreads();
    }
    float S_YY = sm[0];
    __syncthreads();

    // ---- S_XY: ti in [0,32), tj in [32,64) — each tile once ----
    sm[tid] = g_tsum[pair_idx(a, 32 + b)];
    __syncthreads();
    for (int s = 512; s > 0; s >>= 1) {
        if (tid < s) sm[tid] += sm[tid + s];
        __syncthreads();
    }
    float S_XY = sm[0];
    __syncthreads();

    // ---- traces (fp32 trees over 32 diag-tile partials) ----
    sm[tid] = (tid < 32) ? g_ttr[tid] : 0.f;
    __syncthreads();
    for (int s = 16; s > 0; s >>= 1) {
        if (tid < s) sm[tid] += sm[tid + s];
        __syncthreads();
    }
    float T_XX = sm[0];
    __syncthreads();

    sm[tid] = (tid < 32) ? g_ttr[32 + tid] : 0.f;
    __syncthreads();
    for (int s = 16; s > 0; s >>= 1) {
        if (tid < s) sm[tid] += sm[tid + s];
        __syncthreads();
    }
    float T_YY = sm[0];

    if (tid == 0) {
        const float denA = 4096.0f * 4095.0f;   // exactly representable
        const float denC = 4096.0f * 4096.0f;
        float loss = (S_XX - T_XX) / denA;
        loss = loss + (S_YY - T_YY) / denA;
        loss = loss - 2.0f * (S_XY / denC);
        out[0] = loss;
    }
}

// ============================ launch =======================================
extern "C" void kernel_launch(void* const* d_in, const int* in_sizes, int n_in,
                              void* d_out, int out_size) {
    const float* src = (const float*)d_in[0];
    const float* tgt = (const float*)d_in[1];
    float* out = (float*)d_out;

    dim3 grid(NTILE, NTILE);
    k_zero<<<1, 32>>>();
    k_norm<<<NROW, 128>>>(src, tgt);
    k_gram<<<grid, 256>>>();
    k_bw<<<1, 32>>>();
    k_kv<<<grid, 256>>>();
    k_final<<<1, 1024>>>(out);
}

// round 16
// speedup vs baseline: 1.0039x; 1.0039x over previous
#include <cuda_runtime.h>
#include <stdint.h>
#include <math.h>

// ============================ problem constants ============================
#define NROW  8192
#define DIM   512
#define NS    4096
#define NTILE 64            // 8192 / 128
#define NPAIR 2080          // upper-triangular 128x128 tiles

// ============================ device scratch ===============================
__device__ __align__(16) float g_T[NROW * DIM];             // normalized rows (16 MB)
__device__ float  g_sq[NROW];                               // per-row sum of squares
__device__ __align__(16) float g_d2[(size_t)NPAIR * 16384]; // clamped d2 tiles (136 MB)
__device__ double g_sumd2;                                  // Σ d2 (all n² entries)
__device__ float  g_s0;                                     // 1/(16*bandwidth)
__device__ float  g_tsum[NPAIR];                            // per-tile fp32 kv sums (incl. diag)
__device__ float  g_ttr[NTILE];                             // per-diag-tile fp32 trace partials

// ============================ packed f32x2 helpers =========================
// fma.rn.f32x2: two independent IEEE-rn fp32 FMAs per instruction.
// Bitwise identical per lane to scalar fmaf — only the issue rate changes.
__device__ __forceinline__ void fma2(unsigned long long& d,
                                     unsigned long long a,
                                     unsigned long long b) {
    asm("fma.rn.f32x2 %0, %1, %2, %0;" : "+l"(d) : "l"(a), "l"(b));
}
__device__ __forceinline__ unsigned long long pack2(float lo, float hi) {
    unsigned long long r;
    asm("mov.b64 %0, {%1, %2};" : "=l"(r) : "f"(lo), "f"(hi));
    return r;
}
__device__ __forceinline__ void unpack2(unsigned long long v, float& lo, float& hi) {
    asm("mov.b64 {%0, %1}, %2;" : "=f"(lo), "=f"(hi) : "l"(v));
}

// ============================ reductions ===================================
__device__ __forceinline__ double warpRedD(double v) {
    #pragma unroll
    for (int o = 16; o > 0; o >>= 1) v += __shfl_down_sync(0xffffffffu, v, o);
    return v;
}

__device__ __forceinline__ float warpRedF(float v) {
    #pragma unroll
    for (int o = 16; o > 0; o >>= 1) v += __shfl_down_sync(0xffffffffu, v, o);
    return v;
}

__device__ __forceinline__ float blockRed128(float v, float* sh) {
    #pragma unroll
    for (int o = 16; o > 0; o >>= 1) v += __shfl_down_sync(0xffffffffu, v, o);
    int wid = threadIdx.x >> 5, lid = threadIdx.x & 31;
    if (lid == 0) sh[wid] = v;
    __syncthreads();
    if (threadIdx.x == 0) sh[0] = sh[0] + sh[1] + sh[2] + sh[3];
    __syncthreads();
    float out = sh[0];
    __syncthreads();
    return out;
}

__device__ __forceinline__ int pair_idx(int ti, int tj) {
    return ti * NTILE - (ti * (ti - 1)) / 2 + (tj - ti);
}

// ============================ kernels ======================================

__global__ void k_zero() {
    if (threadIdx.x == 0) g_sumd2 = 0.0;
}

// Normalize rows (fp32, exactly as reference), store t and sq.
__global__ void k_norm(const float* __restrict__ src, const float* __restrict__ tgt) {
    __shared__ float sh[4];
    int r = blockIdx.x;
    const float* x = (r < NS) ? (src + (size_t)r * DIM) : (tgt + (size_t)(r - NS) * DIM);
    int tid = threadIdx.x;  // 128 threads, 4 elems each

    float v[4]; float s = 0.f;
    #pragma unroll
    for (int i = 0; i < 4; i++) { v[i] = x[tid + i * 128]; s += v[i] * v[i]; }
    s = blockRed128(s, sh);
    float dn = fmaxf(sqrtf(s), 1e-12f);

    float sq = 0.f;
    #pragma unroll
    for (int i = 0; i < 4; i++) {
        float t = v[i] / dn;
        sq += t * t;
        g_T[(size_t)r * DIM + tid + i * 128] = t;
    }
    sq = blockRed128(sq, sh);
    if (tid == 0) g_sq[r] = sq;
}

// ------------------------------------------------------------------
// Pass A: fp32 gram via packed f32x2 FMA, 128x128 tile, 256 threads,
// 8x8 per thread (j-accumulators packed in pairs).  Each (i,j) chain
// is the same scalar k-ascending fmaf chain as before — bitwise equal.
// Stores clamped d2 per tile and accumulates Σd2 (weight 2 off-diag).
// ------------------------------------------------------------------
__global__ void __launch_bounds__(256, 2) k_gram() {
    int ti = blockIdx.y, tj = blockIdx.x;
    if (tj < ti) return;

    __shared__ float As[16][132];
    __shared__ float Bs[16][132];
    __shared__ float sqi[128], sqj[128];
    __shared__ double sred[8];

    int tid = threadIdx.x;
    if (tid < 128) sqi[tid]       = g_sq[ti * 128 + tid];
    else           sqj[tid - 128] = g_sq[tj * 128 + (tid - 128)];

    unsigned long long acc2[8][4];
    #pragma unroll
    for (int i = 0; i < 8; i++)
        #pragma unroll
        for (int p = 0; p < 4; p++) acc2[i][p] = 0ull;

    const float* TA = g_T + (size_t)ti * 128 * DIM;
    const float* TB = g_T + (size_t)tj * 128 * DIM;

    int tm = (tid >> 4) << 3;
    int tn = (tid & 15) << 3;
    int lr = tid >> 1;
    int lc = (tid & 1) << 3;

    #pragma unroll 1
    for (int k0 = 0; k0 < DIM; k0 += 16) {
        __syncthreads();
        float4 a0 = *(const float4*)(TA + (size_t)lr * DIM + k0 + lc);
        float4 a1 = *(const float4*)(TA + (size_t)lr * DIM + k0 + lc + 4);
        float4 b0 = *(const float4*)(TB + (size_t)lr * DIM + k0 + lc);
        float4 b1 = *(const float4*)(TB + (size_t)lr * DIM + k0 + lc + 4);
        As[lc + 0][lr] = a0.x; As[lc + 1][lr] = a0.y;
        As[lc + 2][lr] = a0.z; As[lc + 3][lr] = a0.w;
        As[lc + 4][lr] = a1.x; As[lc + 5][lr] = a1.y;
        As[lc + 6][lr] = a1.z; As[lc + 7][lr] = a1.w;
        Bs[lc + 0][lr] = b0.x; Bs[lc + 1][lr] = b0.y;
        Bs[lc + 2][lr] = b0.z; Bs[lc + 3][lr] = b0.w;
        Bs[lc + 4][lr] = b1.x; Bs[lc + 5][lr] = b1.y;
        Bs[lc + 6][lr] = b1.z; Bs[lc + 7][lr] = b1.w;
        __syncthreads();

        #pragma unroll
        for (int kk = 0; kk < 16; ++kk) {
            float4 av0 = *(const float4*)(&As[kk][tm]);
            float4 av1 = *(const float4*)(&As[kk][tm + 4]);
            float4 bv0 = *(const float4*)(&Bs[kk][tn]);
            float4 bv1 = *(const float4*)(&Bs[kk][tn + 4]);
            float a[8] = { av0.x, av0.y, av0.z, av0.w, av1.x, av1.y, av1.z, av1.w };
            unsigned long long bp[4] = {
                pack2(bv0.x, bv0.y), pack2(bv0.z, bv0.w),
                pack2(bv1.x, bv1.y), pack2(bv1.z, bv1.w)
            };
            #pragma unroll
            for (int i = 0; i < 8; i++) {
                unsigned long long ap = pack2(a[i], a[i]);
                #pragma unroll
                for (int p = 0; p < 4; p++)
                    fma2(acc2[i][p], ap, bp[p]);
            }
        }
    }

    // unpack to the same scalar accumulators as before
    float acc[8][8];
    #pragma unroll
    for (int i = 0; i < 8; i++)
        #pragma unroll
        for (int p = 0; p < 4; p++)
            unpack2(acc2[i][p], acc[i][2 * p], acc[i][2 * p + 1]);

    size_t base = (size_t)pair_idx(ti, tj) * 16384;
    double dsum = 0.0;
    #pragma unroll
    for (int i = 0; i < 8; i++) {
        #pragma unroll
        for (int j = 0; j < 8; j++) {
            int gi = tm + i, gj = tn + j;
            float d2 = fmaxf(sqi[gi] + sqj[gj] - 2.0f * acc[i][j], 0.0f);
            g_d2[base + (size_t)gi * 128 + gj] = d2;
            dsum += (double)d2;
        }
    }
    if (ti != tj) dsum *= 2.0;

    dsum = warpRedD(dsum);
    int w = tid >> 5, lane = tid & 31;
    if (lane == 0) sred[w] = dsum;
    __syncthreads();
    if (tid == 0) {
        double t = 0.0;
        #pragma unroll
        for (int i = 0; i < 8; i++) t += sred[i];
        atomicAdd(&g_sumd2, t);
    }
}

// bandwidth per reference: sum(d2)/(n²−n) + EPS, then /4
__global__ void k_bw() {
    if (threadIdx.x == 0) {
        double n = (double)NROW;
        double bw = g_sumd2 / (n * n - n) + 1e-8;
        bw *= 0.25;
        g_s0 = (float)(1.0 / (bw * 16.0));
    }
}

// ------------------------------------------------------------------
// Pass B: per-tile kv sums INCLUDING the diagonal (like ref's sum(XX)),
// accumulated in fp32 deterministic trees (reference-faithful precision).
// Also per-diagonal-tile fp32 trace partials.
// ------------------------------------------------------------------
__global__ void __launch_bounds__(256) k_kv() {
    int ti = blockIdx.y, tj = blockIdx.x;
    if (tj < ti) return;

    __shared__ float sred[8];
    __shared__ float str[4];
    int tid = threadIdx.x;
    const float* d2p = g_d2 + (size_t)pair_idx(ti, tj) * 16384;
    float s0 = g_s0;

    // thread t sums contiguous entries [t*64, t*64+64) sequentially in fp32
    float a = 0.f;
    #pragma unroll 4
    for (int e = tid * 64; e < tid * 64 + 64; ++e) {
        float d2 = d2p[e];
        float e4 = expf(-d2 * s0);
        float e3 = e4 * e4, e2 = e3 * e3, e1 = e2 * e2, e0 = e1 * e1;
        a += ((e0 + e1) + (e2 + e3)) + e4;   // kv, diagonal included
    }
    a = warpRedF(a);
    int w = tid >> 5, lane = tid & 31;
    if (lane == 0) sred[w] = a;
    __syncthreads();
    if (tid == 0) {
        float s = ((sred[0] + sred[1]) + (sred[2] + sred[3]))
                + ((sred[4] + sred[5]) + (sred[6] + sred[7]));
        g_tsum[pair_idx(ti, tj)] = s;
    }

    // trace partial for diagonal tiles (fp32 tree over 128 diag entries)
    if (ti == tj) {
        float tr = 0.f;
        if (tid < 128) {
            float d2 = d2p[tid * 129];           // (i,i)
            float e4 = expf(-d2 * s0);
            float e3 = e4 * e4, e2 = e3 * e3, e1 = e2 * e2, e0 = e1 * e1;
            tr = ((e0 + e1) + (e2 + e3)) + e4;
        }
        tr = warpRedF(tr);
        if (tid < 128 && lane == 0) str[w] = tr;
        __syncthreads();
        if (tid == 0)
            g_ttr[ti] = (str[0] + str[1]) + (str[2] + str[3]);
    }
}

// ------------------------------------------------------------------
// Final: region sums via fp32 pairwise trees over tile sums (mirrors
// counted as separate leaves), trace subtraction and loss in fp32 —
// mirroring the reference's fp32 arithmetic structure.
// ------------------------------------------------------------------
__global__ void __launch_bounds__(1024) k_final(float* out) {
    __shared__ float sm[1024];
    int tid = threadIdx.x;
    int a = tid >> 5, b = tid & 31;

    // ---- S_XX: all 32x32 ordered tile pairs in region [0,32) ----
    {
        int lo = min(a, b), hi = max(a, b);
        sm[tid] = g_tsum[pair_idx(lo, hi)];
    }
    __syncthreads();
    for (int s = 512; s > 0; s >>= 1) {
        if (tid < s) sm[tid] += sm[tid + s];
        __syncthreads();
    }
    float S_XX = sm[0];
    __syncthreads();

    // ---- S_YY ----
    {
        int lo = 32 + min(a, b), hi = 32 + max(a, b);
        sm[tid] = g_tsum[pair_idx(lo, hi)];
    }
    __syncthreads();
    for (int s = 512; s > 0; s >>= 1) {
        if (tid < s) sm[tid] += sm[tid + s];
        __syncthreads();
    }
    float S_YY = sm[0];
    __syncthreads();

    // ---- S_XY: ti in [0,32), tj in [32,64) — each tile once ----
    sm[tid] = g_tsum[pair_idx(a, 32 + b)];
    __syncthreads();
    for (int s = 512; s > 0; s >>= 1) {
        if (tid < s) sm[tid] += sm[tid + s];
        __syncthreads();
    }
    float S_XY = sm[0];
    __syncthreads();

    // ---- traces (fp32 trees over 32 diag-tile partials) ----
    sm[tid] = (tid < 32) ? g_ttr[tid] : 0.f;
    __syncthreads();
    for (int s = 16; s > 0; s >>= 1) {
        if (tid < s) sm[tid] += sm[tid + s];
        __syncthreads();
    }
    float T_XX = sm[0];
    __syncthreads();

    sm[tid] = (tid < 32) ? g_ttr[32 + tid] : 0.f;
    __syncthreads();
    for (int s = 16; s > 0; s >>= 1) {
        if (tid < s) sm[tid] += sm[tid + s];
        __syncthreads();
    }
    float T_YY = sm[0];

    if (tid == 0) {
        const float denA = 4096.0f * 4095.0f;   // exactly representable
        const float denC = 4096.0f * 4096.0f;
        float loss = (S_XX - T_XX) / denA;
        loss = loss + (S_YY - T_YY) / denA;
        loss = loss - 2.0f * (S_XY / denC);
        out[0] = loss;
    }
}

// ============================ launch =======================================
extern "C" void kernel_launch(void* const* d_in, const int* in_sizes, int n_in,
                              void* d_out, int out_size) {
    const float* src = (const float*)d_in[0];
    const float* tgt = (const float*)d_in[1];
    float* out = (float*)d_out;

    dim3 grid(NTILE, NTILE);
    k_zero<<<1, 32>>>();
    k_norm<<<NROW, 128>>>(src, tgt);
    k_gram<<<grid, 256>>>();
    k_bw<<<1, 32>>>();
    k_kv<<<grid, 256>>>();
    k_final<<<1, 1024>>>(out);
}